// round 4
// baseline (speedup 1.0000x reference)
#include <cuda_runtime.h>
#include <cstdint>

// Problem constants (fixed shapes per reference)
#define BATCH 4
#define NNODES 4096          // N
#define CH 96                // C
#define N1 (NNODES + 1)      // 4097
#define PS 4                 // pooling_patch_size
#define NPATCH (NNODES / PS) // 1024
// tk = ps / reduction_ratio = 1

// Scratch: v[b][m] = sum_c sigmoid(nodes[b,m,c]) * theta[c]
__device__ float g_v[BATCH * NNODES];

// Exact-enough sigmoid for kernel 1 (tiny op count, keep simple/accurate)
__device__ __forceinline__ float fsig_exact(float x) {
    return __fdividef(1.0f, 1.0f + __expf(-x));
}

// Fast sigmoid for the streaming kernel: 1 MUFU (EX2) + alu bit-trick recip
// + 2 Newton iterations on the fma pipe. Recip rel err ~1.3e-6.
// Valid for d in (small, large) — here d = 1+exp(-x) with |x| <~ 8 always.
__device__ __forceinline__ float fsig(float x) {
    const float t = __expf(-x);                 // FMUL + MUFU.EX2
    const float d = 1.0f + t;
    float y = __int_as_float(0x7EF311C3 - __float_as_int(d));  // ~3.4% err
    y = y * __fmaf_rn(-d, y, 2.0f);             // err -> ~1.2e-3
    y = y * __fmaf_rn(-d, y, 2.0f);             // err -> ~1.3e-6
    return y;
}

// Kernel 1: v[b,m] = dot(sigmoid(x[b,1+m,:]), theta)  (one warp per row,
// one float4 per lane; lanes 24..31 idle on the load). Also copies CLS rows.
__global__ __launch_bounds__(128) void node_score_kernel(
    const float* __restrict__ x, const float* __restrict__ theta,
    float* __restrict__ out)
{
    const int g    = blockIdx.x * 4 + (threadIdx.x >> 5);  // row id 0..16383
    const int lane = threadIdx.x & 31;
    const int b = g >> 12;
    const int m = g & (NNODES - 1);

    float s = 0.0f;
    if (lane < 24) {
        const float4* xr = (const float4*)(x + ((size_t)b * N1 + 1 + m) * CH);
        const float4* th = (const float4*)theta;
        const float4 xv = __ldg(xr + lane);
        const float4 tv = __ldg(th + lane);
        s = fsig_exact(xv.x)*tv.x + fsig_exact(xv.y)*tv.y
          + fsig_exact(xv.z)*tv.z + fsig_exact(xv.w)*tv.w;
    }
#pragma unroll
    for (int off = 16; off > 0; off >>= 1)
        s += __shfl_down_sync(0xffffffffu, s, off);
    if (lane == 0) g_v[g] = s;

    // CLS row copy: 4*96 = 384 elements, handled by the first 3 blocks
    const int idx = blockIdx.x * 128 + threadIdx.x;
    if (idx < BATCH * CH) {
        const int bb = idx / CH, c = idx % CH;
        out[(size_t)bb * (NPATCH + 1) * CH + c] = x[(size_t)bb * N1 * CH + c];
    }
}

// Kernel 2: per patch (b,p): scores for 4 rows = sum_m sigmoid(edge[b,row,m])*v[b,m],
// pick top-1 (first-index tie-break, matching jax top_k). NOTE: the reference
// gathers nodes[b, idx] where idx is the WITHIN-PATCH offset (0..3), not the
// absolute node index — reproduce that exactly.
__global__ __launch_bounds__(256) void score_pool_kernel(
    const float* __restrict__ edge, const float* __restrict__ x,
    float* __restrict__ out)
{
    __shared__ float red[8][4];
    __shared__ float s_scale;
    __shared__ int   s_bidx;

    const int pg = blockIdx.x;         // 0..4095
    const int b  = pg >> 10;
    const int p  = pg & (NPATCH - 1);
    const int tid  = threadIdx.x;
    const int lane = tid & 31;
    const int wid  = tid >> 5;

    const float4* vv4 = (const float4*)(g_v + (b << 12));
    const float4* e0  = (const float4*)(edge + ((size_t)(b << 12) + (p << 2)) * NNODES);
    // row stride in float4 units: 4096/4 = 1024

    float s0 = 0.f, s1 = 0.f, s2 = 0.f, s3 = 0.f;
#pragma unroll
    for (int i = tid; i < 1024; i += 256) {
        const float4 w  = vv4[i];
        const float4 a0 = e0[i];
        const float4 a1 = e0[i + 1024];
        const float4 a2 = e0[i + 2048];
        const float4 a3 = e0[i + 3072];
        s0 += fsig(a0.x)*w.x + fsig(a0.y)*w.y + fsig(a0.z)*w.z + fsig(a0.w)*w.w;
        s1 += fsig(a1.x)*w.x + fsig(a1.y)*w.y + fsig(a1.z)*w.z + fsig(a1.w)*w.w;
        s2 += fsig(a2.x)*w.x + fsig(a2.y)*w.y + fsig(a2.z)*w.z + fsig(a2.w)*w.w;
        s3 += fsig(a3.x)*w.x + fsig(a3.y)*w.y + fsig(a3.z)*w.z + fsig(a3.w)*w.w;
    }

#pragma unroll
    for (int off = 16; off > 0; off >>= 1) {
        s0 += __shfl_down_sync(0xffffffffu, s0, off);
        s1 += __shfl_down_sync(0xffffffffu, s1, off);
        s2 += __shfl_down_sync(0xffffffffu, s2, off);
        s3 += __shfl_down_sync(0xffffffffu, s3, off);
    }
    if (lane == 0) {
        red[wid][0] = s0; red[wid][1] = s1; red[wid][2] = s2; red[wid][3] = s3;
    }
    __syncthreads();

    if (tid == 0) {
        float sc[4];
#pragma unroll
        for (int r = 0; r < 4; r++) {
            float t = 0.f;
#pragma unroll
            for (int w = 0; w < 8; w++) t += red[w][r];
            sc[r] = t;
        }
        // top-1 with lowest-index tie-break (strict >)
        float best = sc[0]; int bi = 0;
#pragma unroll
        for (int r = 1; r < 4; r++)
            if (sc[r] > best) { best = sc[r]; bi = r; }
        s_scale = best + 1.0f;   // pooled = vals*g + g = (vals+1)*g
        s_bidx  = bi;
    }
    __syncthreads();

    if (tid < CH) {
        const int gidx = s_bidx;   // reference uses the raw within-patch index!
        const float g  = x[((size_t)b * N1 + 1 + gidx) * CH + tid];
        out[((size_t)b * (NPATCH + 1) + 1 + p) * CH + tid] = s_scale * g;
    }
}

extern "C" void kernel_launch(void* const* d_in, const int* in_sizes, int n_in,
                              void* d_out, int out_size)
{
    const float* x     = (const float*)d_in[0];  // (4,4097,96) f32
    const float* edge  = (const float*)d_in[1];  // (4,4096,4096) f32
    const float* theta = (const float*)d_in[2];  // (1,96) f32
    float* out = (float*)d_out;                  // (4,1025,96) f32

    node_score_kernel<<<BATCH * NNODES / 4, 128>>>(x, theta, out);
    score_pool_kernel<<<BATCH * NPATCH, 256>>>(edge, x, out);
}

// round 5
// speedup vs baseline: 1.0464x; 1.0464x over previous
#include <cuda_runtime.h>
#include <cstdint>

// Problem constants (fixed shapes per reference)
#define BATCH 4
#define NNODES 4096          // N
#define CH 96                // C
#define N1 (NNODES + 1)      // 4097
#define PS 4                 // pooling_patch_size
#define NPATCH (NNODES / PS) // 1024
// tk = ps / reduction_ratio = 1

// Scratch: v[b][m] = sum_c sigmoid(nodes[b,m,c]) * theta[c]
__device__ float g_v[BATCH * NNODES];

__device__ __forceinline__ float fsig(float x) {
    // fast sigmoid: ~1e-7 rel err (EX2 + RCP on MUFU)
    return __fdividef(1.0f, 1.0f + __expf(-x));
}

// Kernel 1: v[b,m] = dot(sigmoid(x[b,1+m,:]), theta)  (one warp per row)
// Also copies the CLS row x[b,0,:] -> out[b,0,:].  (R2 scalar form — fastest.)
__global__ __launch_bounds__(128) void node_score_kernel(
    const float* __restrict__ x, const float* __restrict__ theta,
    float* __restrict__ out)
{
    const int g    = blockIdx.x * 4 + (threadIdx.x >> 5);  // row id 0..16383
    const int lane = threadIdx.x & 31;
    const int b = g >> 12;
    const int m = g & (NNODES - 1);

    const float* xr = x + ((size_t)b * N1 + 1 + m) * CH;
    float s = 0.0f;
#pragma unroll
    for (int k = 0; k < 3; k++) {
        const int c = lane + 32 * k;
        s += fsig(xr[c]) * theta[c];
    }
#pragma unroll
    for (int off = 16; off > 0; off >>= 1)
        s += __shfl_down_sync(0xffffffffu, s, off);
    if (lane == 0) g_v[g] = s;

    // CLS row copy: 4*96 = 384 elements, handled by the first 3 blocks
    const int idx = blockIdx.x * 128 + threadIdx.x;
    if (idx < BATCH * CH) {
        const int bb = idx / CH, c = idx % CH;
        out[(size_t)bb * (NPATCH + 1) * CH + c] = x[(size_t)bb * N1 * CH + c];
    }
}

// Kernel 2: per patch (b,p): scores for 4 rows = sum_m sigmoid(edge[b,row,m])*v[b,m],
// pick top-1 (first-index tie-break, matching jax top_k). NOTE: the reference
// gathers nodes[b, idx] where idx is the WITHIN-PATCH offset (0..3), not the
// absolute node index — reproduce that exactly.
// Launched with PDL: waits on kernel 1 via grid-dependency sync.
__global__ __launch_bounds__(256) void score_pool_kernel(
    const float* __restrict__ edge, const float* __restrict__ x,
    float* __restrict__ out)
{
    __shared__ float red[8][4];
    __shared__ float s_scale;
    __shared__ int   s_bidx;

    const int pg = blockIdx.x;         // 0..4095
    const int b  = pg >> 10;
    const int p  = pg & (NPATCH - 1);
    const int tid  = threadIdx.x;
    const int lane = tid & 31;
    const int wid  = tid >> 5;

    // PDL: block is resident while node_score_kernel finishes; proceed only
    // once the upstream grid completes (g_v is then visible).
    cudaGridDependencySynchronize();

    const float4* vv4 = (const float4*)(g_v + (b << 12));
    const float4* e0  = (const float4*)(edge + ((size_t)(b << 12) + (p << 2)) * NNODES);
    // row stride in float4 units: 4096/4 = 1024

    float s0 = 0.f, s1 = 0.f, s2 = 0.f, s3 = 0.f;
#pragma unroll
    for (int i = tid; i < 1024; i += 256) {
        const float4 w  = vv4[i];
        const float4 a0 = e0[i];
        const float4 a1 = e0[i + 1024];
        const float4 a2 = e0[i + 2048];
        const float4 a3 = e0[i + 3072];
        s0 += fsig(a0.x)*w.x + fsig(a0.y)*w.y + fsig(a0.z)*w.z + fsig(a0.w)*w.w;
        s1 += fsig(a1.x)*w.x + fsig(a1.y)*w.y + fsig(a1.z)*w.z + fsig(a1.w)*w.w;
        s2 += fsig(a2.x)*w.x + fsig(a2.y)*w.y + fsig(a2.z)*w.z + fsig(a2.w)*w.w;
        s3 += fsig(a3.x)*w.x + fsig(a3.y)*w.y + fsig(a3.z)*w.z + fsig(a3.w)*w.w;
    }

#pragma unroll
    for (int off = 16; off > 0; off >>= 1) {
        s0 += __shfl_down_sync(0xffffffffu, s0, off);
        s1 += __shfl_down_sync(0xffffffffu, s1, off);
        s2 += __shfl_down_sync(0xffffffffu, s2, off);
        s3 += __shfl_down_sync(0xffffffffu, s3, off);
    }
    if (lane == 0) {
        red[wid][0] = s0; red[wid][1] = s1; red[wid][2] = s2; red[wid][3] = s3;
    }
    __syncthreads();

    if (tid == 0) {
        float sc[4];
#pragma unroll
        for (int r = 0; r < 4; r++) {
            float t = 0.f;
#pragma unroll
            for (int w = 0; w < 8; w++) t += red[w][r];
            sc[r] = t;
        }
        // top-1 with lowest-index tie-break (strict >)
        float best = sc[0]; int bi = 0;
#pragma unroll
        for (int r = 1; r < 4; r++)
            if (sc[r] > best) { best = sc[r]; bi = r; }
        s_scale = best + 1.0f;   // pooled = vals*g + g = (vals+1)*g
        s_bidx  = bi;
    }
    __syncthreads();

    if (tid < CH) {
        const int gidx = s_bidx;   // reference uses the raw within-patch index!
        const float g  = x[((size_t)b * N1 + 1 + gidx) * CH + tid];
        out[((size_t)b * (NPATCH + 1) + 1 + p) * CH + tid] = s_scale * g;
    }
}

extern "C" void kernel_launch(void* const* d_in, const int* in_sizes, int n_in,
                              void* d_out, int out_size)
{
    const float* x     = (const float*)d_in[0];  // (4,4097,96) f32
    const float* edge  = (const float*)d_in[1];  // (4,4096,4096) f32
    const float* theta = (const float*)d_in[2];  // (1,96) f32
    float* out = (float*)d_out;                  // (4,1025,96) f32

    node_score_kernel<<<BATCH * NNODES / 4, 128>>>(x, theta, out);

    // Launch kernel 2 with programmatic dependent launch so its blocks are
    // resident (and the launch latency hidden) while kernel 1 drains.
    cudaLaunchConfig_t cfg = {};
    cfg.gridDim  = dim3(BATCH * NPATCH);
    cfg.blockDim = dim3(256);
    cfg.dynamicSmemBytes = 0;
    cfg.stream = 0;
    cudaLaunchAttribute attrs[1];
    attrs[0].id = cudaLaunchAttributeProgrammaticStreamSerialization;
    attrs[0].val.programmaticStreamSerializationAllowed = 1;
    cfg.attrs = attrs;
    cfg.numAttrs = 1;
    cudaLaunchKernelEx(&cfg, score_pool_kernel, edge, x, (float*)d_out);
}